// round 15
// baseline (speedup 1.0000x reference)
#include <cuda_runtime.h>
#include <cuda_fp16.h>
#include <math.h>
#include <stdint.h>

#define C     64
#define A     128
#define HID   256
#define NA    4
#define HW    512
#define NPOS  (HW * HW)
#define TM    256
#define NTILES (NPOS / TM)       // 1024
#define GRID  148
#define NTHREADS 256

// ---- dynamic SMEM byte offsets (no img staging) ----
#define OFF_B1    0              // 4 ks * 8 ntp * 512 = 16384 B (paired layout)
#define OFF_B2    16384          // 8 ks * 8 ntp * 512 = 32768 B
#define OFF_TAIL  49152
#define TF_BASE   (OFF_TAIL / 4)
#define TI_RED    (TF_BASE + 0)      // 16 (l accum + merge L)
#define TI_CB     (TF_BASE + 16)     // 128
#define TI_IB     (TF_BASE + 144)    // 128
#define TI_FW     (TF_BASE + 272)    // 128
#define TI_ACC    (TF_BASE + 400)    // 128 (CTA att partials; merge half-0)
#define TI_SC2    (TF_BASE + 528)    // 128 (merge half-1)
#define TI_SX     (TF_BASE + 656)    // 256 (gates x; merge h)
#define TI_SH     (TF_BASE + 912)    // 256 (gates h0)
#define SMEM_BYTES (OFF_TAIL + 1168 * 4)

__device__ float g_l[GRID];
__device__ float g_acc[GRID * A];
__device__ float g_gates[4 * HID];
__device__ unsigned int g_cnt;       // zero-init; last CTA resets after merge

__device__ __forceinline__ void mma16(float* c, const uint32_t* a, const uint32_t* b) {
    asm volatile("mma.sync.aligned.m16n8k16.row.col.f32.f16.f16.f32 "
        "{%0,%1,%2,%3}, {%4,%5,%6,%7}, {%8,%9}, {%0,%1,%2,%3};"
        : "+f"(c[0]), "+f"(c[1]), "+f"(c[2]), "+f"(c[3])
        : "r"(a[0]), "r"(a[1]), "r"(a[2]), "r"(a[3]), "r"(b[0]), "r"(b[1]));
}

__device__ __forceinline__ uint32_t h2(float lo, float hi) {
    __half2 v = __floats2half2_rn(lo, hi);
    return *reinterpret_cast<uint32_t*>(&v);
}

// ---------------------------------------------------------------------------
// Persistent fused kernel, barrier-free main loop, 32 ROWS PER WARP.
// 256 threads = 8 warps; warp w owns rows w*32..w*32+31 (mt=2 sub-tiles of
// 16 rows) x all 128 cols. Each B LDS.128 now feeds 4 MMAs (2 nt x 2 mt),
// halving LDS-crossbar traffic vs 16-row warps. N is processed in QUARTERS
// (32 cols) so the live accumulator stays acc[2][4][4] (32 regs) and total
// register pressure ~190 (no spill). img is loaded straight into per-lane
// MMA A-fragments (no SMEM staging, no per-tile barrier).
// Blocks 0..127 also compute LSTM gate rows; last CTA merges + LSTM + logits.
// ---------------------------------------------------------------------------
__global__ void __launch_bounds__(NTHREADS, 1)
attn_kernel(const float* __restrict__ img,
            const float* __restrict__ conv_w, const float* __restrict__ conv_b,
            const float* __restrict__ ia_w,   const float* __restrict__ ia_b,
            const float* __restrict__ fa_w,
            const float* __restrict__ action, const float* __restrict__ h0,
            const float* __restrict__ ae_w,   const float* __restrict__ ae_b,
            const float* __restrict__ w_ih,   const float* __restrict__ w_hh,
            const float* __restrict__ b_ih,   const float* __restrict__ b_hh,
            const float* __restrict__ c0,     const float* __restrict__ actor_w,
            const float* __restrict__ actor_b, float* __restrict__ out)
{
    extern __shared__ __align__(1024) float sm[];
    char* smc = (char*)sm;
    __shared__ unsigned int s_isLast;

    const int tid  = threadIdx.x;
    const int lane = tid & 31;
    const int wid  = tid >> 5;        // 8 warps; warp owns rows wid*32..+31
    const int tig  = lane & 3;
    const int g    = lane >> 2;
    const int row0 = wid * 32 + g;    // lane's first owned row (mt=0)

    // ---- one-time: pack B1 (conv_w [128n x 64k]) paired-nt fp16 frags ----
    for (int idx = tid; idx < 4 * 16 * 32 * 2; idx += NTHREADS) {
        int r = idx & 1, l = (idx >> 1) & 31, nt = (idx >> 6) & 15, ks = idx >> 10;
        int n = nt * 8 + (l >> 2);
        int k0 = ks * 16 + (l & 3) * 2 + r * 8;
        *(uint32_t*)(smc + OFF_B1 + (ks * 8 + (nt >> 1)) * 512 + l * 16 + (nt & 1) * 8 + r * 4) =
            h2(conv_w[n * C + k0], conv_w[n * C + k0 + 1]);
    }
    // ---- pack B2 (ia_w [128n x 128k]) ----
    for (int idx = tid; idx < 8 * 16 * 32 * 2; idx += NTHREADS) {
        int r = idx & 1, l = (idx >> 1) & 31, nt = (idx >> 6) & 15, ks = idx >> 10;
        int n = nt * 8 + (l >> 2);
        int k0 = ks * 16 + (l & 3) * 2 + r * 8;
        *(uint32_t*)(smc + OFF_B2 + (ks * 8 + (nt >> 1)) * 512 + l * 16 + (nt & 1) * 8 + r * 4) =
            h2(ia_w[n * A + k0], ia_w[n * A + k0 + 1]);
    }
    if (tid < A) {
        sm[TI_CB + tid] = conv_b[tid];
        sm[TI_IB + tid] = ia_b[tid];
        sm[TI_FW + tid] = fa_w[tid];
        sm[TI_ACC + tid] = 0.f;
    }
    if (tid < 16) sm[TI_RED + tid] = 0.f;
    if (blockIdx.x < 128) {     // gates: x = ae(action) + ae_b, stash h0
        float a0 = action[0], a1 = action[1], a2 = action[2], a3 = action[3];
        sm[TI_SX + tid] = ae_b[tid] + a0 * ae_w[tid * 4] + a1 * ae_w[tid * 4 + 1]
                                    + a2 * ae_w[tid * 4 + 2] + a3 * ae_w[tid * 4 + 3];
        sm[TI_SH + tid] = h0[tid];
    }
    __syncthreads();     // B1/B2/tail visible; main loop needs no further barriers

    // ---- folded LSTM gates: one row per warp for blocks < 128 ----
    if (blockIdx.x < 128) {
        int r = blockIdx.x * 8 + wid;
        const float4* wi = (const float4*)(w_ih + (size_t)r * HID);
        const float4* wh = (const float4*)(w_hh + (size_t)r * HID);
        float s = 0.f;
        #pragma unroll
        for (int j = 0; j < 2; ++j) {
            float4 u = wi[lane * 2 + j], v = wh[lane * 2 + j];
            int k = lane * 8 + j * 4;
            s += u.x * sm[TI_SX + k] + u.y * sm[TI_SX + k + 1]
               + u.z * sm[TI_SX + k + 2] + u.w * sm[TI_SX + k + 3];
            s += v.x * sm[TI_SH + k] + v.y * sm[TI_SH + k + 1]
               + v.z * sm[TI_SH + k + 2] + v.w * sm[TI_SH + k + 3];
        }
        #pragma unroll
        for (int off = 16; off; off >>= 1) s += __shfl_xor_sync(0xffffffffu, s, off);
        if (lane == 0) g_gates[r] = s + b_ih[r] + b_hh[r];
    }

    float attreg[16][2];
    #pragma unroll
    for (int i = 0; i < 16; ++i) { attreg[i][0] = 0.f; attreg[i][1] = 0.f; }
    float l_run = 0.f;

    // ---- direct fragment prefetch of tile blockIdx.x ----
    uint32_t pf[2][16];
    #pragma unroll
    for (int mt = 0; mt < 2; ++mt) {
        const float* base = img + (size_t)blockIdx.x * TM + row0 + mt * 16;
        #pragma unroll
        for (int ks = 0; ks < 4; ++ks) {
            const float* c0p = base + (size_t)(ks * 16 + tig * 2) * NPOS;
            const float* c1p = base + (size_t)(ks * 16 + 8 + tig * 2) * NPOS;
            pf[mt][ks * 4 + 0] = h2(c0p[0], c0p[NPOS]);
            pf[mt][ks * 4 + 1] = h2(c0p[8], c0p[NPOS + 8]);
            pf[mt][ks * 4 + 2] = h2(c1p[0], c1p[NPOS]);
            pf[mt][ks * 4 + 3] = h2(c1p[8], c1p[NPOS + 8]);
        }
    }

    for (int t = blockIdx.x; t < NTILES; t += GRID) {
        uint32_t af[2][8][4];            // fp16 feat frags per mt (full K)
        float s[2][2] = {{0.f, 0.f}, {0.f, 0.f}};

        // ---- GEMM1 (feat = img @ conv_w^T), N-QUARTERS; repack to af ----
        #pragma unroll
        for (int nq = 0; nq < 4; ++nq) {
            float acc[2][4][4];
            #pragma unroll
            for (int mt = 0; mt < 2; ++mt)
                #pragma unroll
                for (int nt = 0; nt < 4; ++nt)
                    #pragma unroll
                    for (int r = 0; r < 4; ++r) acc[mt][nt][r] = 0.f;

            #pragma unroll
            for (int ks = 0; ks < 4; ++ks) {
                #pragma unroll
                for (int np = 0; np < 2; ++np) {
                    uint4 bv = *(const uint4*)(smc + OFF_B1 +
                        (ks * 8 + nq * 2 + np) * 512 + lane * 16);
                    uint32_t b0[2] = {bv.x, bv.y};
                    uint32_t b1[2] = {bv.z, bv.w};
                    mma16(acc[0][np * 2],     &pf[0][ks * 4], b0);
                    mma16(acc[0][np * 2 + 1], &pf[0][ks * 4], b1);
                    mma16(acc[1][np * 2],     &pf[1][ks * 4], b0);
                    mma16(acc[1][np * 2 + 1], &pf[1][ks * 4], b1);
                }
            }

            // bias + relu + repack (quarter nq -> GEMM2 K-steps 2nq, 2nq+1)
            #pragma unroll
            for (int mt = 0; mt < 2; ++mt) {
                #pragma unroll
                for (int nt = 0; nt < 4; ++nt) {
                    float b0 = sm[TI_CB + nq * 32 + nt * 8 + tig * 2];
                    float b1 = sm[TI_CB + nq * 32 + nt * 8 + tig * 2 + 1];
                    acc[mt][nt][0] = fmaxf(acc[mt][nt][0] + b0, 0.f);
                    acc[mt][nt][1] = fmaxf(acc[mt][nt][1] + b1, 0.f);
                    acc[mt][nt][2] = fmaxf(acc[mt][nt][2] + b0, 0.f);
                    acc[mt][nt][3] = fmaxf(acc[mt][nt][3] + b1, 0.f);
                }
                #pragma unroll
                for (int k2 = 0; k2 < 2; ++k2) {
                    af[mt][nq * 2 + k2][0] = h2(acc[mt][k2 * 2][0],     acc[mt][k2 * 2][1]);
                    af[mt][nq * 2 + k2][1] = h2(acc[mt][k2 * 2][2],     acc[mt][k2 * 2][3]);
                    af[mt][nq * 2 + k2][2] = h2(acc[mt][k2 * 2 + 1][0], acc[mt][k2 * 2 + 1][1]);
                    af[mt][nq * 2 + k2][3] = h2(acc[mt][k2 * 2 + 1][2], acc[mt][k2 * 2 + 1][3]);
                }
            }
        }

        // ---- prefetch next tile straight into pf (hidden under GEMM2) ----
        int t2 = t + GRID;
        if (t2 < NTILES) {
            #pragma unroll
            for (int mt = 0; mt < 2; ++mt) {
                const float* base = img + (size_t)t2 * TM + row0 + mt * 16;
                #pragma unroll
                for (int ks = 0; ks < 4; ++ks) {
                    const float* c0p = base + (size_t)(ks * 16 + tig * 2) * NPOS;
                    const float* c1p = base + (size_t)(ks * 16 + 8 + tig * 2) * NPOS;
                    pf[mt][ks * 4 + 0] = h2(c0p[0], c0p[NPOS]);
                    pf[mt][ks * 4 + 1] = h2(c0p[8], c0p[NPOS + 8]);
                    pf[mt][ks * 4 + 2] = h2(c1p[0], c1p[NPOS]);
                    pf[mt][ks * 4 + 3] = h2(c1p[8], c1p[NPOS + 8]);
                }
            }
        }

        // ---- GEMM2 (att1 = feat @ ia_w^T), N-QUARTERS; scores on the fly ----
        #pragma unroll
        for (int nq = 0; nq < 4; ++nq) {
            float acc[2][4][4];
            #pragma unroll
            for (int mt = 0; mt < 2; ++mt)
                #pragma unroll
                for (int nt = 0; nt < 4; ++nt)
                    #pragma unroll
                    for (int r = 0; r < 4; ++r) acc[mt][nt][r] = 0.f;

            #pragma unroll
            for (int ks = 0; ks < 8; ++ks) {
                #pragma unroll
                for (int np = 0; np < 2; ++np) {
                    uint4 bv = *(const uint4*)(smc + OFF_B2 +
                        (ks * 8 + nq * 2 + np) * 512 + lane * 16);
                    uint32_t b0[2] = {bv.x, bv.y};
                    uint32_t b1[2] = {bv.z, bv.w};
                    mma16(acc[0][np * 2],     af[0][ks], b0);
                    mma16(acc[0][np * 2 + 1], af[0][ks], b1);
                    mma16(acc[1][np * 2],     af[1][ks], b0);
                    mma16(acc[1][np * 2 + 1], af[1][ks], b1);
                }
            }

            #pragma unroll
            for (int mt = 0; mt < 2; ++mt) {
                #pragma unroll
                for (int nt = 0; nt < 4; ++nt) {
                    int n0 = nq * 32 + nt * 8 + tig * 2;
                    float ib0 = sm[TI_IB + n0], ib1 = sm[TI_IB + n0 + 1];
                    float fw0 = sm[TI_FW + n0], fw1 = sm[TI_FW + n0 + 1];
                    s[mt][0] += fmaxf(acc[mt][nt][0] + ib0, 0.f) * fw0
                              + fmaxf(acc[mt][nt][1] + ib1, 0.f) * fw1;
                    s[mt][1] += fmaxf(acc[mt][nt][2] + ib0, 0.f) * fw0
                              + fmaxf(acc[mt][nt][3] + ib1, 0.f) * fw1;
                }
            }
        }

        // ---- warp-local softmax weights (max-free; scores are bounded) ----
        float w[2][2];
        #pragma unroll
        for (int mt = 0; mt < 2; ++mt) {
            #pragma unroll
            for (int rh = 0; rh < 2; ++rh) {
                float v = s[mt][rh];
                v += __shfl_xor_sync(0xffffffffu, v, 1);
                v += __shfl_xor_sync(0xffffffffu, v, 2);
                w[mt][rh] = expf(v);
            }
        }
        {
            float v = w[0][0] + w[0][1] + w[1][0] + w[1][1];
            v += __shfl_xor_sync(0xffffffffu, v, 4);
            v += __shfl_xor_sync(0xffffffffu, v, 8);
            v += __shfl_xor_sync(0xffffffffu, v, 16);
            l_run += v;   // identical across the 4 lanes of each group
        }

        // ---- warp-local pooling from af registers (fp16 feat) ----
        #pragma unroll
        for (int mt = 0; mt < 2; ++mt) {
            #pragma unroll
            for (int ks = 0; ks < 8; ++ks) {
                float2 f;
                f = __half22float2(*(__half2*)&af[mt][ks][0]);   // nt=2ks, row g
                attreg[ks * 2][0] += w[mt][0] * f.x;  attreg[ks * 2][1] += w[mt][0] * f.y;
                f = __half22float2(*(__half2*)&af[mt][ks][1]);   // nt=2ks, row g+8
                attreg[ks * 2][0] += w[mt][1] * f.x;  attreg[ks * 2][1] += w[mt][1] * f.y;
                f = __half22float2(*(__half2*)&af[mt][ks][2]);   // nt=2ks+1, row g
                attreg[ks * 2 + 1][0] += w[mt][0] * f.x;  attreg[ks * 2 + 1][1] += w[mt][0] * f.y;
                f = __half22float2(*(__half2*)&af[mt][ks][3]);   // nt=2ks+1, row g+8
                attreg[ks * 2 + 1][0] += w[mt][1] * f.x;  attreg[ks * 2 + 1][1] += w[mt][1] * f.y;
            }
        }
    }

    // ---- CTA epilogue: reduce attreg over groups, emit partials ----
    #pragma unroll
    for (int nt = 0; nt < 16; ++nt) {
        #pragma unroll
        for (int cc = 0; cc < 2; ++cc) {
            float v = attreg[nt][cc];
            v += __shfl_xor_sync(0xffffffffu, v, 4);
            v += __shfl_xor_sync(0xffffffffu, v, 8);
            v += __shfl_xor_sync(0xffffffffu, v, 16);
            if (lane < 4) atomicAdd(&sm[TI_ACC + nt * 8 + lane * 2 + cc], v);
        }
    }
    if (lane == 0) atomicAdd(&sm[TI_RED], l_run);
    __syncthreads();
    if (tid < A) g_acc[blockIdx.x * A + tid] = sm[TI_ACC + tid];
    if (tid == 0) g_l[blockIdx.x] = sm[TI_RED];

    // ---- last-CTA merge: softmax normalize + LSTM + logits ----
    __threadfence();
    __syncthreads();
    if (tid == 0) s_isLast = (atomicAdd(&g_cnt, 1u) == GRID - 1);
    __syncthreads();
    if (!s_isLast) return;
    __threadfence();

    // L = sum g_l
    if (wid == 0) {
        float l = 0.f;
        for (int b = lane; b < GRID; b += 32) l += g_l[b];
        #pragma unroll
        for (int off = 16; off; off >>= 1)
            l += __shfl_xor_sync(0xffffffffu, l, off);
        if (lane == 0) sm[TI_RED + 8] = l;
    }
    // half-column partial sums of g_acc (2 threads per column; 148 = 2*74)
    {
        int a = tid & 127, hh = tid >> 7;
        const float* src = g_acc + (size_t)(hh * 74) * A + a;
        float p = 0.f;
        #pragma unroll 4
        for (int b = 0; b < 74; ++b) p += src[(size_t)b * A];
        sm[(hh ? TI_SC2 : TI_ACC) + a] = p;
    }
    // LSTM activations from g_gates
    {
        float ig = g_gates[tid];
        float fg = g_gates[HID + tid];
        float gg = g_gates[2 * HID + tid];
        float og = g_gates[3 * HID + tid];
        float si = 1.f / (1.f + expf(-ig));
        float sf = 1.f / (1.f + expf(-fg));
        float so = 1.f / (1.f + expf(-og));
        float cc = sf * c0[tid] + si * tanhf(gg);
        float hh = so * tanhf(cc);
        out[4 + tid]       = hh;
        out[4 + HID + tid] = cc;
        sm[TI_SX + tid] = hh;
    }
    __syncthreads();
    if (tid < A)
        sm[TI_ACC + tid] = (sm[TI_ACC + tid] + sm[TI_SC2 + tid]) / sm[TI_RED + 8];
    __syncthreads();

    if (wid < NA) {
        float s = 0.f;
        for (int j = lane; j < A + HID; j += 32) {
            float v = (j < A) ? sm[TI_ACC + j] : sm[TI_SX + j - A];
            s += actor_w[wid * (A + HID) + j] * v;
        }
        #pragma unroll
        for (int off = 16; off; off >>= 1)
            s += __shfl_xor_sync(0xffffffffu, s, off);
        if (lane == 0) out[wid] = s + actor_b[wid];
    }
    if (tid == 0) g_cnt = 0;   // reset for next graph replay
}

// ---------------------------------------------------------------------------
extern "C" void kernel_launch(void* const* d_in, const int* in_sizes, int n_in,
                              void* d_out, int out_size)
{
    const float* img     = (const float*)d_in[0];
    const float* action  = (const float*)d_in[1];
    const float* h0      = (const float*)d_in[2];
    const float* c0      = (const float*)d_in[3];
    const float* conv_w  = (const float*)d_in[4];
    const float* conv_b  = (const float*)d_in[5];
    const float* ae_w    = (const float*)d_in[6];
    const float* ae_b    = (const float*)d_in[7];
    const float* ia_w    = (const float*)d_in[8];
    const float* ia_b    = (const float*)d_in[9];
    // d_in[10] ha_w, d_in[11] ha_b, d_in[13] fa_b: softmax-invariant, unused
    const float* fa_w    = (const float*)d_in[12];
    const float* w_ih    = (const float*)d_in[14];
    const float* w_hh    = (const float*)d_in[15];
    const float* b_ih    = (const float*)d_in[16];
    const float* b_hh    = (const float*)d_in[17];
    const float* actor_w = (const float*)d_in[18];
    const float* actor_b = (const float*)d_in[19];
    float* out = (float*)d_out;

    cudaFuncSetAttribute(attn_kernel,
                         cudaFuncAttributeMaxDynamicSharedMemorySize, SMEM_BYTES);

    attn_kernel<<<GRID, NTHREADS, SMEM_BYTES>>>(img, conv_w, conv_b, ia_w, ia_b, fa_w,
                                                action, h0, ae_w, ae_b,
                                                w_ih, w_hh, b_ih, b_hh,
                                                c0, actor_w, actor_b, out);
}

// round 17
// speedup vs baseline: 1.0147x; 1.0147x over previous
#include <cuda_runtime.h>
#include <cuda_fp16.h>
#include <math.h>
#include <stdint.h>

#define C     64
#define A     128
#define HID   256
#define NA    4
#define HW    512
#define NPOS  (HW * HW)
#define TM    256
#define NTILES (NPOS / TM)       // 1024
#define GRID  148
#define NTHREADS 512

// ---- dynamic SMEM byte offsets (no img staging) ----
#define OFF_B1    0              // 4 ks * 8 ntp * 512 = 16384 B (paired layout)
#define OFF_B2    16384          // 8 ks * 8 ntp * 512 = 32768 B
#define OFF_TAIL  49152
#define TF_BASE   (OFF_TAIL / 4)
#define TI_RED    (TF_BASE + 0)      // 16 (l accum + merge L)
#define TI_CB     (TF_BASE + 16)     // 128
#define TI_IB     (TF_BASE + 144)    // 128
#define TI_FW     (TF_BASE + 272)    // 128
#define TI_ACC    (TF_BASE + 400)    // 128 (CTA att partials; merge q0)
#define TI_SC2    (TF_BASE + 528)    // 128 (merge q1)
#define TI_SC3    (TF_BASE + 656)    // 128 (merge q2)
#define TI_SC4    (TF_BASE + 784)    // 128 (merge q3)
#define TI_SX     (TF_BASE + 912)    // 256 (gates x; merge h)
#define TI_SH     (TF_BASE + 1168)   // 256 (gates h0)
#define SMEM_BYTES (OFF_TAIL + 1424 * 4)

__device__ float g_l[GRID];
__device__ float g_acc[GRID * A];
__device__ float g_gates[4 * HID];
__device__ unsigned int g_cnt;       // zero-init; last CTA resets after merge

__device__ __forceinline__ void mma16(float* c, const uint32_t* a, const uint32_t* b) {
    asm volatile("mma.sync.aligned.m16n8k16.row.col.f32.f16.f16.f32 "
        "{%0,%1,%2,%3}, {%4,%5,%6,%7}, {%8,%9}, {%0,%1,%2,%3};"
        : "+f"(c[0]), "+f"(c[1]), "+f"(c[2]), "+f"(c[3])
        : "r"(a[0]), "r"(a[1]), "r"(a[2]), "r"(a[3]), "r"(b[0]), "r"(b[1]));
}

__device__ __forceinline__ uint32_t h2(float lo, float hi) {
    __half2 v = __floats2half2_rn(lo, hi);
    return *reinterpret_cast<uint32_t*>(&v);
}

// ---------------------------------------------------------------------------
// Persistent fused kernel, barrier-free main loop, 16 rows/warp (R14 base).
// This round: N-QUARTER processing (live acc = 16 regs), explicit B-fragment
// double-buffering across ks (hides LDS latency under MMA issue), de-burst
// prefetch (8 LDGs after each GEMM2 quarter), float2 bias loads.
// Blocks 0..63 also compute LSTM gate rows; last CTA merges + LSTM + logits.
// ---------------------------------------------------------------------------
__global__ void __launch_bounds__(NTHREADS, 1)
attn_kernel(const float* __restrict__ img,
            const float* __restrict__ conv_w, const float* __restrict__ conv_b,
            const float* __restrict__ ia_w,   const float* __restrict__ ia_b,
            const float* __restrict__ fa_w,
            const float* __restrict__ action, const float* __restrict__ h0,
            const float* __restrict__ ae_w,   const float* __restrict__ ae_b,
            const float* __restrict__ w_ih,   const float* __restrict__ w_hh,
            const float* __restrict__ b_ih,   const float* __restrict__ b_hh,
            const float* __restrict__ c0,     const float* __restrict__ actor_w,
            const float* __restrict__ actor_b, float* __restrict__ out)
{
    extern __shared__ __align__(1024) float sm[];
    char* smc = (char*)sm;
    __shared__ unsigned int s_isLast;

    const int tid  = threadIdx.x;
    const int lane = tid & 31;
    const int wid  = tid >> 5;        // 16 warps; warp owns rows wid*16..+15
    const int tig  = lane & 3;
    const int g    = lane >> 2;
    const int row0 = wid * 16 + g;    // this lane's first owned row in tile

    // ---- one-time: pack B1 (conv_w [128n x 64k]) paired-nt fp16 frags ----
    for (int idx = tid; idx < 4 * 16 * 32 * 2; idx += NTHREADS) {
        int r = idx & 1, l = (idx >> 1) & 31, nt = (idx >> 6) & 15, ks = idx >> 10;
        int n = nt * 8 + (l >> 2);
        int k0 = ks * 16 + (l & 3) * 2 + r * 8;
        *(uint32_t*)(smc + OFF_B1 + (ks * 8 + (nt >> 1)) * 512 + l * 16 + (nt & 1) * 8 + r * 4) =
            h2(conv_w[n * C + k0], conv_w[n * C + k0 + 1]);
    }
    // ---- pack B2 (ia_w [128n x 128k]) ----
    for (int idx = tid; idx < 8 * 16 * 32 * 2; idx += NTHREADS) {
        int r = idx & 1, l = (idx >> 1) & 31, nt = (idx >> 6) & 15, ks = idx >> 10;
        int n = nt * 8 + (l >> 2);
        int k0 = ks * 16 + (l & 3) * 2 + r * 8;
        *(uint32_t*)(smc + OFF_B2 + (ks * 8 + (nt >> 1)) * 512 + l * 16 + (nt & 1) * 8 + r * 4) =
            h2(ia_w[n * A + k0], ia_w[n * A + k0 + 1]);
    }
    if (tid < A) {
        sm[TI_CB + tid] = conv_b[tid];
        sm[TI_IB + tid] = ia_b[tid];
        sm[TI_FW + tid] = fa_w[tid];
        sm[TI_ACC + tid] = 0.f;
    }
    if (tid < 16) sm[TI_RED + tid] = 0.f;
    if (blockIdx.x < 64 && tid < HID) {   // gates: x = ae(action) + ae_b, stash h0
        float a0 = action[0], a1 = action[1], a2 = action[2], a3 = action[3];
        sm[TI_SX + tid] = ae_b[tid] + a0 * ae_w[tid * 4] + a1 * ae_w[tid * 4 + 1]
                                    + a2 * ae_w[tid * 4 + 2] + a3 * ae_w[tid * 4 + 3];
        sm[TI_SH + tid] = h0[tid];
    }
    __syncthreads();     // B1/B2/tail visible; main loop needs no further barriers

    // ---- folded LSTM gates: one row per warp for blocks < 64 ----
    if (blockIdx.x < 64) {
        int r = blockIdx.x * 16 + wid;
        const float4* wi = (const float4*)(w_ih + (size_t)r * HID);
        const float4* wh = (const float4*)(w_hh + (size_t)r * HID);
        float s = 0.f;
        #pragma unroll
        for (int j = 0; j < 2; ++j) {
            float4 u = wi[lane * 2 + j], v = wh[lane * 2 + j];
            int k = lane * 8 + j * 4;
            s += u.x * sm[TI_SX + k] + u.y * sm[TI_SX + k + 1]
               + u.z * sm[TI_SX + k + 2] + u.w * sm[TI_SX + k + 3];
            s += v.x * sm[TI_SH + k] + v.y * sm[TI_SH + k + 1]
               + v.z * sm[TI_SH + k + 2] + v.w * sm[TI_SH + k + 3];
        }
        #pragma unroll
        for (int off = 16; off; off >>= 1) s += __shfl_xor_sync(0xffffffffu, s, off);
        if (lane == 0) g_gates[r] = s + b_ih[r] + b_hh[r];
    }

    float attreg[16][2];
    #pragma unroll
    for (int i = 0; i < 16; ++i) { attreg[i][0] = 0.f; attreg[i][1] = 0.f; }
    float l_run = 0.f;

    // ---- direct fragment prefetch of tile blockIdx.x ----
    uint32_t pf[16];
    {
        const float* base = img + (size_t)blockIdx.x * TM + row0;
        #pragma unroll
        for (int ks = 0; ks < 4; ++ks) {
            const float* c0p = base + (size_t)(ks * 16 + tig * 2) * NPOS;
            const float* c1p = base + (size_t)(ks * 16 + 8 + tig * 2) * NPOS;
            pf[ks * 4 + 0] = h2(c0p[0], c0p[NPOS]);
            pf[ks * 4 + 1] = h2(c0p[8], c0p[NPOS + 8]);
            pf[ks * 4 + 2] = h2(c1p[0], c1p[NPOS]);
            pf[ks * 4 + 3] = h2(c1p[8], c1p[NPOS + 8]);
        }
    }

    for (int t = blockIdx.x; t < NTILES; t += GRID) {
        uint32_t af[8][4];               // fp16 feat frags (full K for GEMM2)
        float s0 = 0.f, s1 = 0.f;        // scores for rows row0, row0+8
        const int t2 = t + GRID;
        const float* nbase = img + (size_t)t2 * TM + row0;

        // ---- GEMM1 (feat = img @ conv_w^T), N-QUARTERS, B double-buffered ----
        #pragma unroll
        for (int nq = 0; nq < 4; ++nq) {
            float acc[4][4];
            #pragma unroll
            for (int nt = 0; nt < 4; ++nt)
                #pragma unroll
                for (int r = 0; r < 4; ++r) acc[nt][r] = 0.f;

            uint4 ba = *(const uint4*)(smc + OFF_B1 + (nq * 2 + 0) * 512 + lane * 16);
            uint4 bb = *(const uint4*)(smc + OFF_B1 + (nq * 2 + 1) * 512 + lane * 16);
            #pragma unroll
            for (int ks = 0; ks < 4; ++ks) {
                uint4 na, nb;
                if (ks < 3) {
                    na = *(const uint4*)(smc + OFF_B1 + ((ks + 1) * 8 + nq * 2 + 0) * 512 + lane * 16);
                    nb = *(const uint4*)(smc + OFF_B1 + ((ks + 1) * 8 + nq * 2 + 1) * 512 + lane * 16);
                }
                uint32_t b0[2] = {ba.x, ba.y}, b1[2] = {ba.z, ba.w};
                uint32_t b2[2] = {bb.x, bb.y}, b3[2] = {bb.z, bb.w};
                mma16(acc[0], &pf[ks * 4], b0);
                mma16(acc[1], &pf[ks * 4], b1);
                mma16(acc[2], &pf[ks * 4], b2);
                mma16(acc[3], &pf[ks * 4], b3);
                if (ks < 3) { ba = na; bb = nb; }
            }

            // bias + relu + repack (quarter nq -> GEMM2 K-steps 2nq, 2nq+1)
            #pragma unroll
            for (int nt = 0; nt < 4; ++nt) {
                float2 cb = *(const float2*)&sm[TI_CB + nq * 32 + nt * 8 + tig * 2];
                acc[nt][0] = fmaxf(acc[nt][0] + cb.x, 0.f);
                acc[nt][1] = fmaxf(acc[nt][1] + cb.y, 0.f);
                acc[nt][2] = fmaxf(acc[nt][2] + cb.x, 0.f);
                acc[nt][3] = fmaxf(acc[nt][3] + cb.y, 0.f);
            }
            #pragma unroll
            for (int k2 = 0; k2 < 2; ++k2) {
                af[nq * 2 + k2][0] = h2(acc[k2 * 2][0],     acc[k2 * 2][1]);
                af[nq * 2 + k2][1] = h2(acc[k2 * 2][2],     acc[k2 * 2][3]);
                af[nq * 2 + k2][2] = h2(acc[k2 * 2 + 1][0], acc[k2 * 2 + 1][1]);
                af[nq * 2 + k2][3] = h2(acc[k2 * 2 + 1][2], acc[k2 * 2 + 1][3]);
            }
        }

        // ---- GEMM2 (att1 = feat @ ia_w^T), N-QUARTERS, B double-buffered;
        //      prefetch of next tile de-bursted: 8 LDGs after each quarter ----
        #pragma unroll
        for (int nq = 0; nq < 4; ++nq) {
            float acc[4][4];
            #pragma unroll
            for (int nt = 0; nt < 4; ++nt)
                #pragma unroll
                for (int r = 0; r < 4; ++r) acc[nt][r] = 0.f;

            uint4 ba = *(const uint4*)(smc + OFF_B2 + (nq * 2 + 0) * 512 + lane * 16);
            uint4 bb = *(const uint4*)(smc + OFF_B2 + (nq * 2 + 1) * 512 + lane * 16);
            #pragma unroll
            for (int ks = 0; ks < 8; ++ks) {
                uint4 na, nb;
                if (ks < 7) {
                    na = *(const uint4*)(smc + OFF_B2 + ((ks + 1) * 8 + nq * 2 + 0) * 512 + lane * 16);
                    nb = *(const uint4*)(smc + OFF_B2 + ((ks + 1) * 8 + nq * 2 + 1) * 512 + lane * 16);
                }
                uint32_t b0[2] = {ba.x, ba.y}, b1[2] = {ba.z, ba.w};
                uint32_t b2[2] = {bb.x, bb.y}, b3[2] = {bb.z, bb.w};
                mma16(acc[0], af[ks], b0);
                mma16(acc[1], af[ks], b1);
                mma16(acc[2], af[ks], b2);
                mma16(acc[3], af[ks], b3);
                if (ks < 7) { ba = na; bb = nb; }
            }

            #pragma unroll
            for (int nt = 0; nt < 4; ++nt) {
                int n0 = nq * 32 + nt * 8 + tig * 2;
                float2 ib = *(const float2*)&sm[TI_IB + n0];
                float2 fw = *(const float2*)&sm[TI_FW + n0];
                s0 += fmaxf(acc[nt][0] + ib.x, 0.f) * fw.x + fmaxf(acc[nt][1] + ib.y, 0.f) * fw.y;
                s1 += fmaxf(acc[nt][2] + ib.x, 0.f) * fw.x + fmaxf(acc[nt][3] + ib.y, 0.f) * fw.y;
            }

            // de-burst prefetch: group nq of next tile's A fragments
            if (t2 < NTILES) {
                const float* c0p = nbase + (size_t)(nq * 16 + tig * 2) * NPOS;
                const float* c1p = nbase + (size_t)(nq * 16 + 8 + tig * 2) * NPOS;
                pf[nq * 4 + 0] = h2(c0p[0], c0p[NPOS]);
                pf[nq * 4 + 1] = h2(c0p[8], c0p[NPOS + 8]);
                pf[nq * 4 + 2] = h2(c1p[0], c1p[NPOS]);
                pf[nq * 4 + 3] = h2(c1p[8], c1p[NPOS + 8]);
            }
        }

        // ---- warp-local softmax weights (max-free; scores are bounded) ----
        s0 += __shfl_xor_sync(0xffffffffu, s0, 1);
        s0 += __shfl_xor_sync(0xffffffffu, s0, 2);
        s1 += __shfl_xor_sync(0xffffffffu, s1, 1);
        s1 += __shfl_xor_sync(0xffffffffu, s1, 2);
        float w0 = expf(s0), w1 = expf(s1);
        {
            float v = w0 + w1;
            v += __shfl_xor_sync(0xffffffffu, v, 4);
            v += __shfl_xor_sync(0xffffffffu, v, 8);
            v += __shfl_xor_sync(0xffffffffu, v, 16);
            l_run += v;   // identical across the 4 lanes of each group
        }

        // ---- warp-local pooling from af registers (fp16 feat) ----
        #pragma unroll
        for (int ks = 0; ks < 8; ++ks) {
            float2 f;
            f = __half22float2(*(__half2*)&af[ks][0]);   // nt=2ks, row g
            attreg[ks * 2][0] += w0 * f.x;  attreg[ks * 2][1] += w0 * f.y;
            f = __half22float2(*(__half2*)&af[ks][1]);   // nt=2ks, row g+8
            attreg[ks * 2][0] += w1 * f.x;  attreg[ks * 2][1] += w1 * f.y;
            f = __half22float2(*(__half2*)&af[ks][2]);   // nt=2ks+1, row g
            attreg[ks * 2 + 1][0] += w0 * f.x;  attreg[ks * 2 + 1][1] += w0 * f.y;
            f = __half22float2(*(__half2*)&af[ks][3]);   // nt=2ks+1, row g+8
            attreg[ks * 2 + 1][0] += w1 * f.x;  attreg[ks * 2 + 1][1] += w1 * f.y;
        }
    }

    // ---- CTA epilogue: reduce attreg over groups, emit partials ----
    #pragma unroll
    for (int nt = 0; nt < 16; ++nt) {
        #pragma unroll
        for (int cc = 0; cc < 2; ++cc) {
            float v = attreg[nt][cc];
            v += __shfl_xor_sync(0xffffffffu, v, 4);
            v += __shfl_xor_sync(0xffffffffu, v, 8);
            v += __shfl_xor_sync(0xffffffffu, v, 16);
            if (lane < 4) atomicAdd(&sm[TI_ACC + nt * 8 + lane * 2 + cc], v);
        }
    }
    if (lane == 0) atomicAdd(&sm[TI_RED], l_run);
    __syncthreads();
    if (tid < A) g_acc[blockIdx.x * A + tid] = sm[TI_ACC + tid];
    if (tid == 0) g_l[blockIdx.x] = sm[TI_RED];

    // ---- last-CTA merge: softmax normalize + LSTM + logits ----
    __threadfence();
    __syncthreads();
    if (tid == 0) s_isLast = (atomicAdd(&g_cnt, 1u) == GRID - 1);
    __syncthreads();
    if (!s_isLast) return;
    __threadfence();

    // L = sum g_l
    if (wid == 0) {
        float l = 0.f;
        for (int b = lane; b < GRID; b += 32) l += g_l[b];
        #pragma unroll
        for (int off = 16; off; off >>= 1)
            l += __shfl_xor_sync(0xffffffffu, l, off);
        if (lane == 0) sm[TI_RED + 8] = l;
    }
    // quarter-column partial sums of g_acc (4 threads per column; 148 = 4*37)
    {
        int a = tid & 127, q = tid >> 7;           // q in 0..3
        const float* src = g_acc + (size_t)(q * 37) * A + a;
        float p = 0.f;
        #pragma unroll 4
        for (int b = 0; b < 37; ++b) p += src[(size_t)b * A];
        int dst = (q == 0) ? TI_ACC : (q == 1) ? TI_SC2 : (q == 2) ? TI_SC3 : TI_SC4;
        sm[dst + a] = p;
    }
    // LSTM activations from g_gates
    if (tid < HID) {
        float ig = g_gates[tid];
        float fg = g_gates[HID + tid];
        float gg = g_gates[2 * HID + tid];
        float og = g_gates[3 * HID + tid];
        float si = 1.f / (1.f + expf(-ig));
        float sf = 1.f / (1.f + expf(-fg));
        float so = 1.f / (1.f + expf(-og));
        float cc = sf * c0[tid] + si * tanhf(gg);
        float hh = so * tanhf(cc);
        out[4 + tid]       = hh;
        out[4 + HID + tid] = cc;
        sm[TI_SX + tid] = hh;
    }
    __syncthreads();
    if (tid < A)
        sm[TI_ACC + tid] = (sm[TI_ACC + tid] + sm[TI_SC2 + tid]
                          + sm[TI_SC3 + tid] + sm[TI_SC4 + tid]) / sm[TI_RED + 8];
    __syncthreads();

    if (wid < NA) {
        float s = 0.f;
        for (int j = lane; j < A + HID; j += 32) {
            float v = (j < A) ? sm[TI_ACC + j] : sm[TI_SX + j - A];
            s += actor_w[wid * (A + HID) + j] * v;
        }
        #pragma unroll
        for (int off = 16; off; off >>= 1)
            s += __shfl_xor_sync(0xffffffffu, s, off);
        if (lane == 0) out[wid] = s + actor_b[wid];
    }
    if (tid == 0) g_cnt = 0;   // reset for next graph replay
}

// ---------------------------------------------------------------------------
extern "C" void kernel_launch(void* const* d_in, const int* in_sizes, int n_in,
                              void* d_out, int out_size)
{
    const float* img     = (const float*)d_in[0];
    const float* action  = (const float*)d_in[1];
    const float* h0      = (const float*)d_in[2];
    const float* c0      = (const float*)d_in[3];
    const float* conv_w  = (const float*)d_in[4];
    const float* conv_b  = (const float*)d_in[5];
    const float* ae_w    = (const float*)d_in[6];
    const float* ae_b    = (const float*)d_in[7];
    const float* ia_w    = (const float*)d_in[8];
    const float* ia_b    = (const float*)d_in[9];
    // d_in[10] ha_w, d_in[11] ha_b, d_in[13] fa_b: softmax-invariant, unused
    const float* fa_w    = (const float*)d_in[12];
    const float* w_ih    = (const float*)d_in[14];
    const float* w_hh    = (const float*)d_in[15];
    const float* b_ih    = (const float*)d_in[16];
    const float* b_hh    = (const float*)d_in[17];
    const float* actor_w = (const float*)d_in[18];
    const float* actor_b = (const float*)d_in[19];
    float* out = (float*)d_out;

    cudaFuncSetAttribute(attn_kernel,
                         cudaFuncAttributeMaxDynamicSharedMemorySize, SMEM_BYTES);

    attn_kernel<<<GRID, NTHREADS, SMEM_BYTES>>>(img, conv_w, conv_b, ia_w, ia_b, fa_w,
                                                action, h0, ae_w, ae_b,
                                                w_ih, w_hh, b_ih, b_hh,
                                                c0, actor_w, actor_b, out);
}